// round 15
// baseline (speedup 1.0000x reference)
#include <cuda_runtime.h>
#include <cuda_bf16.h>
#include <cuda_fp16.h>
#include <math.h>
#include <stdint.h>

// ---------------- problem constants ----------------
#define NB   8
#define NS   256
#define NP   16
#define ND   512
#define NH   8
#define HD   64
#define NL   6
#define NF   2048
#define NV   65536
#define NTOK (NB * NS)   // 2048

// ---------------- scratch (device globals; no allocation) ----------------
__device__ float g_x  [NTOK * ND];          // residual stream (fp32)
__device__ float g_qkv[NTOK * 3 * ND];      // qkv projection (fp32)

// split-fp16 activation tiles (hi|lo 2KB halves of 4KB blocks, swizzled)
__device__ uint8_t s_xn [NTOK * ND * 4];
__device__ uint8_t s_o  [NTOK * ND * 4];
__device__ uint8_t s_h  [NTOK * NF * 4];
// fp16 single tiles (2KB blocks) for weights + vocab A
__device__ uint8_t s_win[NL * 3 * ND * ND * 2];
__device__ uint8_t s_wo [NL * ND * ND * 2];
__device__ uint8_t s_w1 [NL * NF * ND * 2];
__device__ uint8_t s_w2 [(size_t)NL * ND * NF * 2];
__device__ uint8_t s_xf [NTOK * ND * 2];
__device__ uint8_t s_wv [(size_t)NV * ND * 2];

__device__ __forceinline__ uint32_t smem_u32(const void* p) {
    uint32_t a;
    asm("{ .reg .u64 t; cvta.to.shared.u64 t, %1; cvt.u32.u64 %0, t; }" : "=r"(a) : "l"(p));
    return a;
}

// ---------------- split / store helpers ----------------
__device__ __forceinline__ void store_split2_f16(uint8_t* base, int K, int row, int col,
                                                 float a, float b) {
    __half ha = __float2half_rn(a);
    __half hb = __float2half_rn(b);
    __half2 hi = __halves2half2(ha, hb);
    __half2 lo = __floats2half2_rn(a - __half2float(ha), b - __half2float(hb));
    size_t blk = (size_t)(row >> 6) * (K >> 4) + (col >> 4);
    uint32_t off = (uint32_t)((row & 63) * 32 +
                   ((((col >> 3) & 1) ^ ((row >> 2) & 1)) << 4) + (col & 7) * 2);
    *(__half2*)(base + blk * 4096 + off) = hi;
    *(__half2*)(base + blk * 4096 + 2048 + off) = lo;
}
__device__ __forceinline__ void store_h2(uint8_t* base, int K, int row, int col,
                                         float a, float b) {
    __half2 h = __floats2half2_rn(a, b);
    size_t blk = (size_t)(row >> 6) * (K >> 4) + (col >> 4);
    uint32_t off = (uint32_t)((row & 63) * 32 +
                   ((((col >> 3) & 1) ^ ((row >> 2) & 1)) << 4) + (col & 7) * 2);
    *(__half2*)(base + blk * 2048 + off) = h;
}

// ---------------- weight conversion (fp32 [R,K] -> fp16 single tiles) --------
// Panel-based, coalesced reads: one 256-thread block converts a 64-row panel.
// Consecutive threads read consecutive 8-element chunks of the same row.
// Output bytes identical to the previous per-chunk kernel.
__global__ void convert_w_h(const float* __restrict__ src, uint8_t* __restrict__ dst,
                            int K) {
    const int cpr = K >> 3;                  // 8-elem chunks per row (pow2)
    const int sh  = 31 - __clz((unsigned)cpr);
    const int nch = cpr * 64;                // chunks in this panel
    const float* sp = src + (size_t)blockIdx.x * 64 * K;
    uint8_t* dp = dst + (size_t)blockIdx.x * (K >> 4) * 2048;

    for (int g2 = threadIdx.x; g2 < nch; g2 += 256) {
        const int row = g2 >> sh;
        const int c8  = g2 & (cpr - 1);
        const float* p = sp + (size_t)row * K + c8 * 8;
        float4 v0 = *(const float4*)p, v1 = *(const float4*)(p + 4);
        __half2 h0 = __floats2half2_rn(v0.x, v0.y);
        __half2 h1 = __floats2half2_rn(v0.z, v0.w);
        __half2 h2 = __floats2half2_rn(v1.x, v1.y);
        __half2 h3 = __floats2half2_rn(v1.z, v1.w);
        uint4 hv;
        hv.x = *(unsigned*)&h0; hv.y = *(unsigned*)&h1;
        hv.z = *(unsigned*)&h2; hv.w = *(unsigned*)&h3;
        const int s16 = c8 >> 1, kc = c8 & 1;
        const uint32_t off = (uint32_t)(row * 32 + ((kc ^ ((row >> 2) & 1)) << 4));
        *(uint4*)(dp + (size_t)s16 * 2048 + off) = hv;
    }
}

// ---------------- tokenize + embed ----------------
__global__ void tokenize_embed_kernel(const float* __restrict__ patches,
                                      const float* __restrict__ masked_token,
                                      const float* __restrict__ partial_params,
                                      const float* __restrict__ emb_w,
                                      const float* __restrict__ emb_b) {
    const int tok = blockIdx.x;
    const int tid = threadIdx.x;   // 128 threads
    __shared__ float proc[NP];

    if (tid == 0) {
        const float* f = patches + (size_t)tok * NP;
        bool anyMask = false, anyBin = false;
        int firstBin = -1;
        float fp[NP];
        #pragma unroll
        for (int p = 0; p < NP; p++) {
            float v = f[p];
            fp[p] = v;
            bool m = fabsf(v - 0.5f) < 0.1f;
            if (m) anyMask = true;
            else { anyBin = true; if (firstBin < 0) firstBin = p; }
        }
        if (!anyBin) {
            #pragma unroll
            for (int p = 0; p < NP; p++) proc[p] = masked_token[p];
        } else if (anyMask) {
            int ptok = firstBin * 2 + (int)rintf(fp[firstBin]);
            const float* pp = partial_params + ptok * NP;
            #pragma unroll
            for (int p = 0; p < NP; p++) proc[p] = pp[p];
        } else {
            #pragma unroll
            for (int p = 0; p < NP; p++) proc[p] = fp[p];
        }
    }
    __syncthreads();

    for (int d = tid; d < ND; d += blockDim.x) {
        const float* w = emb_w + d * NP;
        float s = emb_b[d];
        #pragma unroll
        for (int p = 0; p < NP; p++) s += proc[p] * w[p];
        g_x[(size_t)tok * ND + d] = s;
    }
}

// ---------------- layernorm (fp32 in -> split-fp16 tile out) ----------------
__global__ void ln_kernel(const float* __restrict__ in, uint8_t* __restrict__ out,
                          const float* __restrict__ gamma, const float* __restrict__ beta) {
    const int tok = blockIdx.x;
    const int tid = threadIdx.x;   // 256
    const float2 v = ((const float2*)(in + (size_t)tok * ND))[tid];

    float s  = v.x + v.y;
    float sq = v.x * v.x + v.y * v.y;
    #pragma unroll
    for (int off = 16; off; off >>= 1) {
        s  += __shfl_xor_sync(0xffffffffu, s,  off);
        sq += __shfl_xor_sync(0xffffffffu, sq, off);
    }
    __shared__ float rs[8], rq[8], stats[2];
    if ((tid & 31) == 0) { rs[tid >> 5] = s; rq[tid >> 5] = sq; }
    __syncthreads();
    if (tid == 0) {
        float S = 0.f, Q = 0.f;
        #pragma unroll
        for (int i = 0; i < 8; i++) { S += rs[i]; Q += rq[i]; }
        float mean = S * (1.0f / ND);
        float var  = Q * (1.0f / ND) - mean * mean;
        stats[0] = mean;
        stats[1] = rsqrtf(var + 1e-5f);
    }
    __syncthreads();
    const float mean = stats[0], inv = stats[1];
    float2 g2 = ((const float2*)gamma)[tid];
    float2 b2 = ((const float2*)beta)[tid];
    float ox = (v.x - mean) * inv * g2.x + b2.x;
    float oy = (v.y - mean) * inv * g2.y + b2.y;
    store_split2_f16(out, ND, tok, tid * 2, ox, oy);
}

// ---------------- fused attention (smem K/V, 512 threads, split out) --------
#define ATTN_SMEM (224 * 1024)

__global__ __launch_bounds__(512) void attn_kernel(const float* __restrict__ rel) {
    extern __shared__ float sm[];
    float* Ks = sm;            // [256][64] rotated rows
    float* Vs = sm + 16384;    // [256][64]
    float* Qs = sm + 32768;    // [128][64]
    float* Wb = sm + 40960;    // [16 warps][256][4]

    const int idx = blockIdx.x;
    const int qc = idx & 1;
    const int h  = (idx >> 1) & (NH - 1);
    const int b  = idx >> 4;
    const int tid = threadIdx.x, wid = tid >> 5, L = tid & 31;

    const size_t base = (size_t)(b * NS) * (3 * ND) + h * HD;

    {
        const int dc = (tid & 15) * 4;
        int t = tid >> 4;   // 0..31
        #pragma unroll 4
        for (int pass = 0; pass < 8; pass++, t += 32) {
            const float* kR = g_qkv + base + ND + (size_t)t * (3 * ND);
            float4 kv = *(const float4*)(kR + dc);
            const int p = (dc + 4 * (t & 15)) & 63;
            *(float4*)(Ks + t * 64 + p) = kv;
            const float* vR = g_qkv + base + 2 * ND + (size_t)t * (3 * ND);
            *(float4*)(Vs + t * 64 + dc) = *(const float4*)(vR + dc);
        }
        int q = tid >> 4;
        #pragma unroll 4
        for (int pass = 0; pass < 4; pass++, q += 32) {
            const float* qR = g_qkv + base + (size_t)(qc * 128 + q) * (3 * ND);
            *(float4*)(Qs + q * 64 + dc) = *(const float4*)(qR + dc);
        }
    }
    __syncthreads();

    float* wb = Wb + wid * 1024;
    const int rot = 4 * (L & 15);

    for (int g4 = 0; g4 < 2; g4++) {
        const int q0 = wid * 8 + g4 * 4;
        const int sRow = qc * 128 + q0;

        float sc[4][8];
        #pragma unroll
        for (int qi = 0; qi < 4; qi++)
            #pragma unroll
            for (int j = 0; j < 8; j++) sc[qi][j] = 0.f;

        #pragma unroll
        for (int dd = 0; dd < 16; dd++) {
            const int d = dd * 4;
            float4 qv[4];
            #pragma unroll
            for (int qi = 0; qi < 4; qi++)
                qv[qi] = *(const float4*)(Qs + (q0 + qi) * 64 + d);
            const int p = (d + rot) & 63;
            #pragma unroll
            for (int j = 0; j < 8; j++) {
                float4 k4 = *(const float4*)(Ks + (L + 32 * j) * 64 + p);
                #pragma unroll
                for (int qi = 0; qi < 4; qi++)
                    sc[qi][j] += qv[qi].x * k4.x + qv[qi].y * k4.y +
                                 qv[qi].z * k4.z + qv[qi].w * k4.w;
            }
        }

        #pragma unroll
        for (int qi = 0; qi < 4; qi++) {
            const float* rrow = rel + (size_t)(sRow + qi) * NS;
            float m = -1e30f;
            #pragma unroll
            for (int j = 0; j < 8; j++) {
                float v = sc[qi][j] * 0.125f + rrow[L + 32 * j];
                sc[qi][j] = v;
                m = fmaxf(m, v);
            }
            #pragma unroll
            for (int off = 16; off; off >>= 1)
                m = fmaxf(m, __shfl_xor_sync(0xffffffffu, m, off));
            float ssum = 0.f;
            #pragma unroll
            for (int j = 0; j < 8; j++) { sc[qi][j] = expf(sc[qi][j] - m); ssum += sc[qi][j]; }
            #pragma unroll
            for (int off = 16; off; off >>= 1)
                ssum += __shfl_xor_sync(0xffffffffu, ssum, off);
            const float inv = 1.0f / ssum;
            #pragma unroll
            for (int j = 0; j < 8; j++) sc[qi][j] *= inv;
        }

        #pragma unroll
        for (int j = 0; j < 8; j++)
            *(float4*)(wb + (L + 32 * j) * 4) =
                make_float4(sc[0][j], sc[1][j], sc[2][j], sc[3][j]);
        __syncwarp();

        float2 acc[4];
        #pragma unroll
        for (int qi = 0; qi < 4; qi++) acc[qi] = make_float2(0.f, 0.f);
        #pragma unroll 4
        for (int t = 0; t < NS; t++) {
            float2 v2 = *(const float2*)(Vs + t * 64 + 2 * L);
            float4 w4 = *(const float4*)(wb + t * 4);
            acc[0].x += w4.x * v2.x; acc[0].y += w4.x * v2.y;
            acc[1].x += w4.y * v2.x; acc[1].y += w4.y * v2.y;
            acc[2].x += w4.z * v2.x; acc[2].y += w4.z * v2.y;
            acc[3].x += w4.w * v2.x; acc[3].y += w4.w * v2.y;
        }
        #pragma unroll
        for (int qi = 0; qi < 4; qi++)
            store_split2_f16(s_o, ND, b * NS + sRow + qi, h * HD + 2 * L,
                             acc[qi].x, acc[qi].y);
        __syncwarp();
    }
}

// ---------------- GEMM common macros ----------------
#define MMA_FP16(d, a0,a1,a2,a3, b0,b1)                                         \
    asm volatile("mma.sync.aligned.m16n8k16.row.col.f32.f16.f16.f32 "           \
                 "{%0,%1,%2,%3}, {%4,%5,%6,%7}, {%8,%9}, {%0,%1,%2,%3};"        \
                 : "+f"(d[0]), "+f"(d[1]), "+f"(d[2]), "+f"(d[3])               \
                 : "r"(a0), "r"(a1), "r"(a2), "r"(a3), "r"(b0), "r"(b1))

#define LDSM4(r, addr)                                                          \
    asm volatile("ldmatrix.sync.aligned.m8n8.x4.shared.b16 {%0,%1,%2,%3}, [%4];"\
                 : "=r"((r)[0]), "=r"((r)[1]), "=r"((r)[2]), "=r"((r)[3])       \
                 : "r"(addr))

#define CP16(dst, src)                                                          \
    asm volatile("cp.async.cg.shared.global [%0], [%1], 16;" :: "r"(dst), "l"(src))
#define CP_COMMIT() asm volatile("cp.async.commit_group;" ::: "memory")
#define CP_WAIT2()  asm volatile("cp.async.wait_group 2;" ::: "memory")
#define CP_WAIT1()  asm volatile("cp.async.wait_group 1;" ::: "memory")

__device__ __forceinline__ uint32_t tile_off(int m, int kc) {   // 4KB blocks
    return (uint32_t)((m >> 6) * 4096 + (m & 63) * 32 +
                      ((kc ^ ((m >> 2) & 1)) << 4));
}
__device__ __forceinline__ uint32_t tile_off_h(int m, int kc) { // 2KB blocks
    return (uint32_t)((m >> 6) * 2048 + (m & 63) * 32 +
                      ((kc ^ ((m >> 2) & 1)) << 4));
}

// ---------------- 2-term split-fp16 GEMM (layer GEMMs), 2 k-chunks/stage ----
// (round-14 verified config, unchanged)
template <int EPI>
__global__ __launch_bounds__(256, 2)
void gemm_2t(const uint8_t* __restrict__ A, const uint8_t* __restrict__ W,
             const float* __restrict__ bias, const float* __restrict__ res,
             void* __restrict__ Cout, int M, int N, int K) {
    constexpr int CH   = 8192;
    constexpr int ST   = 2 * CH;
    constexpr int NSTG = 4;

    extern __shared__ uint8_t smem[];
    const uint32_t sb = smem_u32(smem);

    const int tid = threadIdx.x;
    const int bm = blockIdx.x * 64;
    const int bn = blockIdx.y * 128;
    const int wid = tid >> 5, lane = tid & 31;
    const int g = lane >> 2, t4 = lane & 3;
    const int wm = (wid >> 2) * 32;
    const int wn = (wid & 3) * 32;

    const int S  = K >> 4;
    const int SP = S >> 1;

    const int o0 = tid * 16;
    const int o1 = 4096 + tid * 16;
    const uint8_t* src0 = A + (size_t)blockIdx.x * S * 4096 + o0;
    const uint8_t* src1;
    {
        const int nt0 = blockIdx.y * 2;
        const int wsel = (o1 - 4096) >> 11;
        src1 = W + (size_t)(nt0 + wsel) * S * 2048 + ((o1 - 4096) & 2047);
    }

    const int sel = lane >> 3, ri = lane & 7;
    uint32_t aOffH[2], bOff[2];
    #pragma unroll
    for (int mf = 0; mf < 2; mf++) {
        const int m = wm + mf * 16 + (sel & 1) * 8 + ri;
        aOffH[mf] = tile_off(m, sel >> 1);
    }
    #pragma unroll
    for (int p = 0; p < 2; p++) {
        const int n = wn + p * 16 + (sel >> 1) * 8 + ri;
        bOff[p] = 4096 + tile_off_h(n, sel & 1);
    }

    float acc[2][4][4];
    #pragma unroll
    for (int i = 0; i < 2; i++)
        #pragma unroll
        for (int j = 0; j < 4; j++)
            #pragma unroll
            for (int c = 0; c < 4; c++) acc[i][j][c] = 0.f;

    #pragma unroll
    for (int s = 0; s < NSTG - 1; s++) {
        const uint32_t dst = sb + s * ST;
        CP16(dst + o0, src0);
        CP16(dst + o1, src1);
        CP16(dst + CH + o0, src0 + 4096);
        CP16(dst + CH + o1, src1 + 2048);
        src0 += 8192; src1 += 4096;
        CP_COMMIT();
    }

    for (int s = 0; s < SP; s++) {
        CP_WAIT2();
        __syncthreads();

        const uint32_t stg = sb + (uint32_t)((s & 3) * ST);
        #pragma unroll
        for (int j = 0; j < 2; j++) {
            const uint32_t cofs = stg + j * CH;
            uint32_t aH[2][4], aL[2][4], bS[2][4];
            #pragma unroll
            for (int mf = 0; mf < 2; mf++) {
                LDSM4(aH[mf], cofs + aOffH[mf]);
                LDSM4(aL[mf], cofs + aOffH[mf] + 2048);
            }
            #pragma unroll
            for (int p = 0; p < 2; p++) LDSM4(bS[p], cofs + bOff[p]);

            #pragma unroll
            for (int mf = 0; mf < 2; mf++)
                #pragma unroll
                for (int nf = 0; nf < 4; nf++) {
                    const int p = nf >> 1, q = (nf & 1) * 2;
                    MMA_FP16(acc[mf][nf], aH[mf][0], aH[mf][1], aH[mf][2], aH[mf][3],
                             bS[p][q], bS[p][q + 1]);
                    MMA_FP16(acc[mf][nf], aL[mf][0], aL[mf][1], aL[mf][2], aL[mf][3],
                             bS[p][q], bS[p][q + 1]);
                }
        }

        if (s + NSTG - 1 < SP) {
            const uint32_t dst = sb + (uint32_t)(((s + NSTG - 1) & 3) * ST);
            CP16(dst + o0, src0);
            CP16(dst + o1, src1);
            CP16(dst + CH + o0, src0 + 4096);
            CP16(dst + CH + o1, src1 + 2048);
            src0 += 8192; src1 += 4096;
        }
        CP_COMMIT();
    }

    // ---- epilogue ----
    #pragma unroll
    for (int mf = 0; mf < 2; mf++) {
        const int r0 = bm + wm + mf * 16 + g;
        #pragma unroll
        for (int nf = 0; nf < 4; nf++) {
            const int c0 = bn + wn + nf * 8 + 2 * t4;
            const float2 bv = *(const float2*)(bias + c0);
            float v00 = acc[mf][nf][0] + bv.x;
            float v01 = acc[mf][nf][1] + bv.y;
            float v10 = acc[mf][nf][2] + bv.x;
            float v11 = acc[mf][nf][3] + bv.y;
            if (EPI == 2) {
                v00 = v00 * 0.5f * (1.0f + erff(v00 * 0.70710678118654752f));
                v01 = v01 * 0.5f * (1.0f + erff(v01 * 0.70710678118654752f));
                v10 = v10 * 0.5f * (1.0f + erff(v10 * 0.70710678118654752f));
                v11 = v11 * 0.5f * (1.0f + erff(v11 * 0.70710678118654752f));
                uint8_t* C = (uint8_t*)Cout;
                store_split2_f16(C, N, r0,     c0, v00, v01);
                store_split2_f16(C, N, r0 + 8, c0, v10, v11);
            } else if (EPI == 3) {
                const size_t i0 = (size_t)r0 * N + c0;
                const size_t i1 = (size_t)(r0 + 8) * N + c0;
                const float2 r0v = *(const float2*)(res + i0);
                const float2 r1v = *(const float2*)(res + i1);
                v00 += r0v.x; v01 += r0v.y; v10 += r1v.x; v11 += r1v.y;
                uint8_t* C = (uint8_t*)Cout;
                store_h2(C, N, r0,     c0, v00, v01);
                store_h2(C, N, r0 + 8, c0, v10, v11);
            } else {
                float* C = (float*)Cout;
                const size_t i0 = (size_t)r0 * N + c0;
                const size_t i1 = (size_t)(r0 + 8) * N + c0;
                if (EPI == 1) {
                    const float2 r0v = *(const float2*)(res + i0);
                    const float2 r1v = *(const float2*)(res + i1);
                    v00 += r0v.x; v01 += r0v.y; v10 += r1v.x; v11 += r1v.y;
                }
                *(float2*)(C + i0) = make_float2(v00, v01);
                *(float2*)(C + i1) = make_float2(v10, v11);
            }
        }
    }
}

// ---------------- fp16 single-term GEMM (vocab), 4 k-chunks/stage -----------
// TM=128 x 128. Stage = 4 chunks = 32 KB, 3 stages = 96 KB, 2 CTAs/SM.
__global__ __launch_bounds__(256, 2)
void gemm_h(const uint8_t* __restrict__ A, const uint8_t* __restrict__ W,
            const float* __restrict__ bias, float* __restrict__ C,
            int M, int N, int K) {
    constexpr int ST   = 32768;
    constexpr int NSTG = 3;

    extern __shared__ uint8_t smem[];
    const uint32_t sb = smem_u32(smem);

    const int tid = threadIdx.x;
    const int bm = blockIdx.x * 128;
    const int bn = blockIdx.y * 128;
    const int wid = tid >> 5, lane = tid & 31;
    const int g = lane >> 2, t4 = lane & 3;
    const int wm = (wid >> 2) * 64;
    const int wn = (wid & 3) * 32;

    const int S = K >> 4;        // 32 k-chunks
    const int SP = S >> 2;       // 8 pipeline stages

    const int o0 = tid * 16;
    const int o1 = 4096 + tid * 16;
    const uint8_t* src0;
    const uint8_t* src1;
    {
        const int mt0 = blockIdx.x * 2;
        const int nt0 = blockIdx.y * 2;
        const uint8_t* blkp[4];
        blkp[0] = A + (size_t)(mt0 + 0) * S * 2048;
        blkp[1] = A + (size_t)(mt0 + 1) * S * 2048;
        blkp[2] = W + (size_t)(nt0 + 0) * S * 2048;
        blkp[3] = W + (size_t)(nt0 + 1) * S * 2048;
        src0 = blkp[o0 >> 11] + (o0 & 2047);
        src1 = blkp[o1 >> 11] + (o1 & 2047);
    }

    const int sel = lane >> 3, ri = lane & 7;
    uint32_t aOff[4], bOff[2];
    #pragma unroll
    for (int mf = 0; mf < 4; mf++) {
        const int m = wm + mf * 16 + (sel & 1) * 8 + ri;
        aOff[mf] = tile_off_h(m, sel >> 1);
    }
    #pragma unroll
    for (int p = 0; p < 2; p++) {
        const int n = wn + p * 16 + (sel >> 1) * 8 + ri;
        bOff[p] = 4096 + tile_off_h(n, sel & 1);
    }

    float acc[4][4][4];
    #pragma unroll
    for (int i = 0; i < 4; i++)
        #pragma unroll
        for (int j = 0; j < 4; j++)
            #pragma unroll
            for (int c = 0; c < 4; c++) acc[i][j][c] = 0.f;

    // prologue: 2 stages x 4 chunks
    #pragma unroll
    for (int s = 0; s < NSTG - 1; s++) {
        const uint32_t dst = sb + s * ST;
        #pragma unroll
        for (int c = 0; c < 4; c++) {
            CP16(dst + c * 8192 + o0, src0 + c * 2048);
            CP16(dst + c * 8192 + o1, src1 + c * 2048);
        }
        src0 += 8192; src1 += 8192;
        CP_COMMIT();
    }

    int cur = 0, nxt = 2;   // stage slots mod 3
    for (int s = 0; s < SP; s++) {
        CP_WAIT1();
        __syncthreads();

        const uint32_t stg = sb + (uint32_t)(cur * ST);
        #pragma unroll
        for (int j = 0; j < 4; j++) {
            const uint32_t cofs = stg + j * 8192;
            uint32_t aF[4][4], bF[2][4];
            #pragma unroll
            for (int mf = 0; mf < 4; mf++) LDSM4(aF[mf], cofs + aOff[mf]);
            #pragma unroll
            for (int p = 0; p < 2; p++)    LDSM4(bF[p], cofs + bOff[p]);

            #pragma unroll
            for (int mf = 0; mf < 4; mf++)
                #pragma unroll
                for (int nf = 0; nf < 4; nf++) {
                    const int p = nf >> 1, q = (nf & 1) * 2;
                    MMA_FP16(acc[mf][nf], aF[mf][0], aF[mf][1], aF[mf][2], aF[mf][3],
                             bF[p][q], bF[p][q + 1]);
                }
        }

        if (s + NSTG - 1 < SP) {
            const uint32_t dst = sb + (uint32_t)(nxt * ST);
            #pragma unroll
            for (int c = 0; c < 4; c++) {
                CP16(dst + c * 8192 + o0, src0 + c * 2048);
                CP16(dst + c * 8192 + o1, src1 + c * 2048);
            }
            src0 += 8192; src1 += 8192;
        }
        CP_COMMIT();
        cur = (cur == 2) ? 0 : cur + 1;
        nxt = (nxt == 2) ? 0 : nxt + 1;
    }

    #pragma unroll
    for (int mf = 0; mf < 4; mf++) {
        const int r0 = bm + wm + mf * 16 + g;
        #pragma unroll
        for (int nf = 0; nf < 4; nf++) {
            const int c0 = bn + wn + nf * 8 + 2 * t4;
            const float2 bv = *(const float2*)(bias + c0);
            const size_t i0 = (size_t)r0 * N + c0;
            const size_t i1 = (size_t)(r0 + 8) * N + c0;
            *(float2*)(C + i0) = make_float2(acc[mf][nf][0] + bv.x, acc[mf][nf][1] + bv.y);
            *(float2*)(C + i1) = make_float2(acc[mf][nf][2] + bv.x, acc[mf][nf][3] + bv.y);
        }
    }
}

// ---------------- launch ----------------
extern "C" void kernel_launch(void* const* d_in, const int* in_sizes, int n_in,
                              void* d_out, int out_size) {
    const float* patches        = (const float*)d_in[0];
    const float* masked_token   = (const float*)d_in[3];
    const float* partial_params = (const float*)d_in[4];
    const float* emb_w          = (const float*)d_in[5];
    const float* emb_b          = (const float*)d_in[6];
    const float* ln1_g          = (const float*)d_in[7];
    const float* ln1_b          = (const float*)d_in[8];
    const float* in_proj_w      = (const float*)d_in[9];
    const float* in_proj_b      = (const float*)d_in[10];
    const float* out_proj_w     = (const float*)d_in[11];
    const float* out_proj_b     = (const float*)d_in[12];
    const float* rel_pos        = (const float*)d_in[13];
    const float* ln2_g          = (const float*)d_in[14];
    const float* ln2_b          = (const float*)d_in[15];
    const float* ffn_w1         = (const float*)d_in[16];
    const float* ffn_b1         = (const float*)d_in[17];
    const float* ffn_w2         = (const float*)d_in[18];
    const float* ffn_b2         = (const float*)d_in[19];
    const float* outp_w         = (const float*)d_in[20];
    const float* outp_b         = (const float*)d_in[21];
    float* out = (float*)d_out;

    float *x, *qkv;
    uint8_t *xn, *o, *h, *xf, *win, *wo, *w1, *w2, *wv;
    cudaGetSymbolAddress((void**)&x,   g_x);
    cudaGetSymbolAddress((void**)&qkv, g_qkv);
    cudaGetSymbolAddress((void**)&xn,  s_xn);
    cudaGetSymbolAddress((void**)&o,   s_o);
    cudaGetSymbolAddress((void**)&h,   s_h);
    cudaGetSymbolAddress((void**)&xf,  s_xf);
    cudaGetSymbolAddress((void**)&win, s_win);
    cudaGetSymbolAddress((void**)&wo,  s_wo);
    cudaGetSymbolAddress((void**)&w1,  s_w1);
    cudaGetSymbolAddress((void**)&w2,  s_w2);
    cudaGetSymbolAddress((void**)&wv,  s_wv);

    cudaFuncSetAttribute(attn_kernel, cudaFuncAttributeMaxDynamicSharedMemorySize, ATTN_SMEM);
    cudaFuncSetAttribute((const void*)gemm_2t<0>, cudaFuncAttributeMaxDynamicSharedMemorySize, 65536);
    cudaFuncSetAttribute((const void*)gemm_2t<1>, cudaFuncAttributeMaxDynamicSharedMemorySize, 65536);
    cudaFuncSetAttribute((const void*)gemm_2t<2>, cudaFuncAttributeMaxDynamicSharedMemorySize, 65536);
    cudaFuncSetAttribute((const void*)gemm_2t<3>, cudaFuncAttributeMaxDynamicSharedMemorySize, 65536);
    cudaFuncSetAttribute((const void*)gemm_h, cudaFuncAttributeMaxDynamicSharedMemorySize, 98304);

    // ---- convert all weights to fp16 single tiles (panel-coalesced) ----
    convert_w_h<<<NL * 3 * ND / 64, 256>>>(in_proj_w,  win, ND);
    convert_w_h<<<NL * ND / 64,     256>>>(out_proj_w, wo,  ND);
    convert_w_h<<<NL * NF / 64,     256>>>(ffn_w1,     w1,  ND);
    convert_w_h<<<NL * ND / 64,     256>>>(ffn_w2,     w2,  NF);
    convert_w_h<<<NV / 64,          256>>>(outp_w,     wv,  ND);

    tokenize_embed_kernel<<<NTOK, 128>>>(patches, masked_token, partial_params, emb_w, emb_b);

    for (int l = 0; l < NL; l++) {
        ln_kernel<<<NTOK, 256>>>(x, xn, ln1_g + l * ND, ln1_b + l * ND);

        gemm_2t<0><<<dim3(NTOK / 64, 3 * ND / 128), 256, 65536>>>(
            xn, win + (size_t)l * 3 * ND * ND * 2, in_proj_b + l * 3 * ND,
            nullptr, qkv, NTOK, 3 * ND, ND);

        attn_kernel<<<NB * NH * 2, 512, ATTN_SMEM>>>(rel_pos + (size_t)l * NS * NS);

        gemm_2t<1><<<dim3(NTOK / 64, ND / 128), 256, 65536>>>(
            o, wo + (size_t)l * ND * ND * 2, out_proj_b + l * ND,
            x, x, NTOK, ND, ND);

        ln_kernel<<<NTOK, 256>>>(x, xn, ln2_g + l * ND, ln2_b + l * ND);

        gemm_2t<2><<<dim3(NTOK / 64, NF / 128), 256, 65536>>>(
            xn, w1 + (size_t)l * NF * ND * 2, ffn_b1 + l * NF,
            nullptr, h, NTOK, NF, ND);

        if (l < NL - 1) {
            gemm_2t<1><<<dim3(NTOK / 64, ND / 128), 256, 65536>>>(
                h, w2 + (size_t)l * ND * NF * 2, ffn_b2 + l * ND,
                x, x, NTOK, ND, NF);
        } else {
            gemm_2t<3><<<dim3(NTOK / 64, ND / 128), 256, 65536>>>(
                h, w2 + (size_t)l * ND * NF * 2, ffn_b2 + l * ND,
                x, xf, NTOK, ND, NF);
        }
    }

    gemm_h<<<dim3(NTOK / 128, NV / 128), 256, 98304>>>(
        xf, wv, outp_b, out, NTOK, NV, ND);
}

// round 16
// speedup vs baseline: 1.0228x; 1.0228x over previous
#include <cuda_runtime.h>
#include <cuda_bf16.h>
#include <cuda_fp16.h>
#include <math.h>
#include <stdint.h>

// ---------------- problem constants ----------------
#define NB   8
#define NS   256
#define NP   16
#define ND   512
#define NH   8
#define HD   64
#define NL   6
#define NF   2048
#define NV   65536
#define NTOK (NB * NS)   // 2048

// ---------------- scratch (device globals; no allocation) ----------------
__device__ float g_x  [NTOK * ND];          // residual stream (fp32)
__device__ float g_qkv[NTOK * 3 * ND];      // qkv projection (fp32)

// split-fp16 activation tiles (hi|lo 2KB halves of 4KB blocks, swizzled)
__device__ uint8_t s_xn [NTOK * ND * 4];
__device__ uint8_t s_o  [NTOK * ND * 4];
__device__ uint8_t s_h  [NTOK * NF * 4];
// fp16 single tiles (2KB blocks) for weights + vocab A
__device__ uint8_t s_win[NL * 3 * ND * ND * 2];
__device__ uint8_t s_wo [NL * ND * ND * 2];
__device__ uint8_t s_w1 [NL * NF * ND * 2];
__device__ uint8_t s_w2 [(size_t)NL * ND * NF * 2];
__device__ uint8_t s_xf [NTOK * ND * 2];
__device__ uint8_t s_wv [(size_t)NV * ND * 2];

__device__ __forceinline__ uint32_t smem_u32(const void* p) {
    uint32_t a;
    asm("{ .reg .u64 t; cvta.to.shared.u64 t, %1; cvt.u32.u64 %0, t; }" : "=r"(a) : "l"(p));
    return a;
}

// ---------------- split / store helpers ----------------
__device__ __forceinline__ void store_split2_f16(uint8_t* base, int K, int row, int col,
                                                 float a, float b) {
    __half ha = __float2half_rn(a);
    __half hb = __float2half_rn(b);
    __half2 hi = __halves2half2(ha, hb);
    __half2 lo = __floats2half2_rn(a - __half2float(ha), b - __half2float(hb));
    size_t blk = (size_t)(row >> 6) * (K >> 4) + (col >> 4);
    uint32_t off = (uint32_t)((row & 63) * 32 +
                   ((((col >> 3) & 1) ^ ((row >> 2) & 1)) << 4) + (col & 7) * 2);
    *(__half2*)(base + blk * 4096 + off) = hi;
    *(__half2*)(base + blk * 4096 + 2048 + off) = lo;
}
__device__ __forceinline__ void store_h2(uint8_t* base, int K, int row, int col,
                                         float a, float b) {
    __half2 h = __floats2half2_rn(a, b);
    size_t blk = (size_t)(row >> 6) * (K >> 4) + (col >> 4);
    uint32_t off = (uint32_t)((row & 63) * 32 +
                   ((((col >> 3) & 1) ^ ((row >> 2) & 1)) << 4) + (col & 7) * 2);
    *(__half2*)(base + blk * 2048 + off) = h;
}

// ---------------- weight conversion (fp32 [R,K] -> fp16 single tiles) --------
// Per-chunk mapping (round-14 verified: ~2.9 TB/s, high occupancy).
__global__ void convert_w_h(const float* __restrict__ src, uint8_t* __restrict__ dst,
                            int K, int nChunks) {
    int ct = blockIdx.x * 256 + threadIdx.x;
    if (ct >= nChunks) return;
    int within = ct & 127;
    int blk = ct >> 7;
    int r = within >> 1, kc = within & 1;
    int stages = K >> 4;
    int rt = blk / stages, s = blk - rt * stages;
    const float* p = src + (size_t)(rt * 64 + r) * K + s * 16 + kc * 8;
    float4 v0 = *(const float4*)p, v1 = *(const float4*)(p + 4);
    __half2 h0 = __floats2half2_rn(v0.x, v0.y);
    __half2 h1 = __floats2half2_rn(v0.z, v0.w);
    __half2 h2 = __floats2half2_rn(v1.x, v1.y);
    __half2 h3 = __floats2half2_rn(v1.z, v1.w);
    uint4 hv;
    hv.x = *(unsigned*)&h0; hv.y = *(unsigned*)&h1;
    hv.z = *(unsigned*)&h2; hv.w = *(unsigned*)&h3;
    uint32_t off = (uint32_t)(r * 32 + ((kc ^ ((r >> 2) & 1)) << 4));
    *(uint4*)(dst + (size_t)blk * 2048 + off) = hv;
}

// ---------------- tokenize + embed ----------------
__global__ void tokenize_embed_kernel(const float* __restrict__ patches,
                                      const float* __restrict__ masked_token,
                                      const float* __restrict__ partial_params,
                                      const float* __restrict__ emb_w,
                                      const float* __restrict__ emb_b) {
    const int tok = blockIdx.x;
    const int tid = threadIdx.x;   // 128 threads
    __shared__ float proc[NP];

    if (tid == 0) {
        const float* f = patches + (size_t)tok * NP;
        bool anyMask = false, anyBin = false;
        int firstBin = -1;
        float fp[NP];
        #pragma unroll
        for (int p = 0; p < NP; p++) {
            float v = f[p];
            fp[p] = v;
            bool m = fabsf(v - 0.5f) < 0.1f;
            if (m) anyMask = true;
            else { anyBin = true; if (firstBin < 0) firstBin = p; }
        }
        if (!anyBin) {
            #pragma unroll
            for (int p = 0; p < NP; p++) proc[p] = masked_token[p];
        } else if (anyMask) {
            int ptok = firstBin * 2 + (int)rintf(fp[firstBin]);
            const float* pp = partial_params + ptok * NP;
            #pragma unroll
            for (int p = 0; p < NP; p++) proc[p] = pp[p];
        } else {
            #pragma unroll
            for (int p = 0; p < NP; p++) proc[p] = fp[p];
        }
    }
    __syncthreads();

    for (int d = tid; d < ND; d += blockDim.x) {
        const float* w = emb_w + d * NP;
        float s = emb_b[d];
        #pragma unroll
        for (int p = 0; p < NP; p++) s += proc[p] * w[p];
        g_x[(size_t)tok * ND + d] = s;
    }
}

// ---------------- layernorm (fp32 in -> split-fp16 tile out) ----------------
__global__ void ln_kernel(const float* __restrict__ in, uint8_t* __restrict__ out,
                          const float* __restrict__ gamma, const float* __restrict__ beta) {
    const int tok = blockIdx.x;
    const int tid = threadIdx.x;   // 256
    const float2 v = ((const float2*)(in + (size_t)tok * ND))[tid];

    float s  = v.x + v.y;
    float sq = v.x * v.x + v.y * v.y;
    #pragma unroll
    for (int off = 16; off; off >>= 1) {
        s  += __shfl_xor_sync(0xffffffffu, s,  off);
        sq += __shfl_xor_sync(0xffffffffu, sq, off);
    }
    __shared__ float rs[8], rq[8], stats[2];
    if ((tid & 31) == 0) { rs[tid >> 5] = s; rq[tid >> 5] = sq; }
    __syncthreads();
    if (tid == 0) {
        float S = 0.f, Q = 0.f;
        #pragma unroll
        for (int i = 0; i < 8; i++) { S += rs[i]; Q += rq[i]; }
        float mean = S * (1.0f / ND);
        float var  = Q * (1.0f / ND) - mean * mean;
        stats[0] = mean;
        stats[1] = rsqrtf(var + 1e-5f);
    }
    __syncthreads();
    const float mean = stats[0], inv = stats[1];
    float2 g2 = ((const float2*)gamma)[tid];
    float2 b2 = ((const float2*)beta)[tid];
    float ox = (v.x - mean) * inv * g2.x + b2.x;
    float oy = (v.y - mean) * inv * g2.y + b2.y;
    store_split2_f16(out, ND, tok, tid * 2, ox, oy);
}

// ---------------- fused attention (smem K/V, 512 threads, split out) --------
#define ATTN_SMEM (224 * 1024)

__global__ __launch_bounds__(512) void attn_kernel(const float* __restrict__ rel) {
    extern __shared__ float sm[];
    float* Ks = sm;            // [256][64] rotated rows
    float* Vs = sm + 16384;    // [256][64]
    float* Qs = sm + 32768;    // [128][64]
    float* Wb = sm + 40960;    // [16 warps][256][4]

    const int idx = blockIdx.x;
    const int qc = idx & 1;
    const int h  = (idx >> 1) & (NH - 1);
    const int b  = idx >> 4;
    const int tid = threadIdx.x, wid = tid >> 5, L = tid & 31;

    const size_t base = (size_t)(b * NS) * (3 * ND) + h * HD;

    {
        const int dc = (tid & 15) * 4;
        int t = tid >> 4;   // 0..31
        #pragma unroll 4
        for (int pass = 0; pass < 8; pass++, t += 32) {
            const float* kR = g_qkv + base + ND + (size_t)t * (3 * ND);
            float4 kv = *(const float4*)(kR + dc);
            const int p = (dc + 4 * (t & 15)) & 63;
            *(float4*)(Ks + t * 64 + p) = kv;
            const float* vR = g_qkv + base + 2 * ND + (size_t)t * (3 * ND);
            *(float4*)(Vs + t * 64 + dc) = *(const float4*)(vR + dc);
        }
        int q = tid >> 4;
        #pragma unroll 4
        for (int pass = 0; pass < 4; pass++, q += 32) {
            const float* qR = g_qkv + base + (size_t)(qc * 128 + q) * (3 * ND);
            *(float4*)(Qs + q * 64 + dc) = *(const float4*)(qR + dc);
        }
    }
    __syncthreads();

    float* wb = Wb + wid * 1024;
    const int rot = 4 * (L & 15);

    for (int g4 = 0; g4 < 2; g4++) {
        const int q0 = wid * 8 + g4 * 4;
        const int sRow = qc * 128 + q0;

        float sc[4][8];
        #pragma unroll
        for (int qi = 0; qi < 4; qi++)
            #pragma unroll
            for (int j = 0; j < 8; j++) sc[qi][j] = 0.f;

        #pragma unroll
        for (int dd = 0; dd < 16; dd++) {
            const int d = dd * 4;
            float4 qv[4];
            #pragma unroll
            for (int qi = 0; qi < 4; qi++)
                qv[qi] = *(const float4*)(Qs + (q0 + qi) * 64 + d);
            const int p = (d + rot) & 63;
            #pragma unroll
            for (int j = 0; j < 8; j++) {
                float4 k4 = *(const float4*)(Ks + (L + 32 * j) * 64 + p);
                #pragma unroll
                for (int qi = 0; qi < 4; qi++)
                    sc[qi][j] += qv[qi].x * k4.x + qv[qi].y * k4.y +
                                 qv[qi].z * k4.z + qv[qi].w * k4.w;
            }
        }

        #pragma unroll
        for (int qi = 0; qi < 4; qi++) {
            const float* rrow = rel + (size_t)(sRow + qi) * NS;
            float m = -1e30f;
            #pragma unroll
            for (int j = 0; j < 8; j++) {
                float v = sc[qi][j] * 0.125f + rrow[L + 32 * j];
                sc[qi][j] = v;
                m = fmaxf(m, v);
            }
            #pragma unroll
            for (int off = 16; off; off >>= 1)
                m = fmaxf(m, __shfl_xor_sync(0xffffffffu, m, off));
            float ssum = 0.f;
            #pragma unroll
            for (int j = 0; j < 8; j++) { sc[qi][j] = expf(sc[qi][j] - m); ssum += sc[qi][j]; }
            #pragma unroll
            for (int off = 16; off; off >>= 1)
                ssum += __shfl_xor_sync(0xffffffffu, ssum, off);
            const float inv = 1.0f / ssum;
            #pragma unroll
            for (int j = 0; j < 8; j++) sc[qi][j] *= inv;
        }

        #pragma unroll
        for (int j = 0; j < 8; j++)
            *(float4*)(wb + (L + 32 * j) * 4) =
                make_float4(sc[0][j], sc[1][j], sc[2][j], sc[3][j]);
        __syncwarp();

        float2 acc[4];
        #pragma unroll
        for (int qi = 0; qi < 4; qi++) acc[qi] = make_float2(0.f, 0.f);
        #pragma unroll 4
        for (int t = 0; t < NS; t++) {
            float2 v2 = *(const float2*)(Vs + t * 64 + 2 * L);
            float4 w4 = *(const float4*)(wb + t * 4);
            acc[0].x += w4.x * v2.x; acc[0].y += w4.x * v2.y;
            acc[1].x += w4.y * v2.x; acc[1].y += w4.y * v2.y;
            acc[2].x += w4.z * v2.x; acc[2].y += w4.z * v2.y;
            acc[3].x += w4.w * v2.x; acc[3].y += w4.w * v2.y;
        }
        #pragma unroll
        for (int qi = 0; qi < 4; qi++)
            store_split2_f16(s_o, ND, b * NS + sRow + qi, h * HD + 2 * L,
                             acc[qi].x, acc[qi].y);
        __syncwarp();
    }
}

// ---------------- GEMM common macros ----------------
#define MMA_FP16(d, a0,a1,a2,a3, b0,b1)                                         \
    asm volatile("mma.sync.aligned.m16n8k16.row.col.f32.f16.f16.f32 "           \
                 "{%0,%1,%2,%3}, {%4,%5,%6,%7}, {%8,%9}, {%0,%1,%2,%3};"        \
                 : "+f"(d[0]), "+f"(d[1]), "+f"(d[2]), "+f"(d[3])               \
                 : "r"(a0), "r"(a1), "r"(a2), "r"(a3), "r"(b0), "r"(b1))

#define LDSM4(r, addr)                                                          \
    asm volatile("ldmatrix.sync.aligned.m8n8.x4.shared.b16 {%0,%1,%2,%3}, [%4];"\
                 : "=r"((r)[0]), "=r"((r)[1]), "=r"((r)[2]), "=r"((r)[3])       \
                 : "r"(addr))

#define CP16(dst, src)                                                          \
    asm volatile("cp.async.cg.shared.global [%0], [%1], 16;" :: "r"(dst), "l"(src))
#define CP_COMMIT() asm volatile("cp.async.commit_group;" ::: "memory")
#define CP_WAIT2()  asm volatile("cp.async.wait_group 2;" ::: "memory")
#define CP_WAIT1()  asm volatile("cp.async.wait_group 1;" ::: "memory")

__device__ __forceinline__ uint32_t tile_off(int m, int kc) {   // 4KB blocks
    return (uint32_t)((m >> 6) * 4096 + (m & 63) * 32 +
                      ((kc ^ ((m >> 2) & 1)) << 4));
}
__device__ __forceinline__ uint32_t tile_off_h(int m, int kc) { // 2KB blocks
    return (uint32_t)((m >> 6) * 2048 + (m & 63) * 32 +
                      ((kc ^ ((m >> 2) & 1)) << 4));
}

// ---------------- 2-term split-fp16 GEMM (layer GEMMs), 2 k-chunks/stage ----
template <int EPI>
__global__ __launch_bounds__(256, 2)
void gemm_2t(const uint8_t* __restrict__ A, const uint8_t* __restrict__ W,
             const float* __restrict__ bias, const float* __restrict__ res,
             void* __restrict__ Cout, int M, int N, int K) {
    constexpr int CH   = 8192;
    constexpr int ST   = 2 * CH;
    constexpr int NSTG = 4;

    extern __shared__ uint8_t smem[];
    const uint32_t sb = smem_u32(smem);

    const int tid = threadIdx.x;
    const int bm = blockIdx.x * 64;
    const int bn = blockIdx.y * 128;
    const int wid = tid >> 5, lane = tid & 31;
    const int g = lane >> 2, t4 = lane & 3;
    const int wm = (wid >> 2) * 32;
    const int wn = (wid & 3) * 32;

    const int S  = K >> 4;
    const int SP = S >> 1;

    const int o0 = tid * 16;
    const int o1 = 4096 + tid * 16;
    const uint8_t* src0 = A + (size_t)blockIdx.x * S * 4096 + o0;
    const uint8_t* src1;
    {
        const int nt0 = blockIdx.y * 2;
        const int wsel = (o1 - 4096) >> 11;
        src1 = W + (size_t)(nt0 + wsel) * S * 2048 + ((o1 - 4096) & 2047);
    }

    const int sel = lane >> 3, ri = lane & 7;
    uint32_t aOffH[2], bOff[2];
    #pragma unroll
    for (int mf = 0; mf < 2; mf++) {
        const int m = wm + mf * 16 + (sel & 1) * 8 + ri;
        aOffH[mf] = tile_off(m, sel >> 1);
    }
    #pragma unroll
    for (int p = 0; p < 2; p++) {
        const int n = wn + p * 16 + (sel >> 1) * 8 + ri;
        bOff[p] = 4096 + tile_off_h(n, sel & 1);
    }

    float acc[2][4][4];
    #pragma unroll
    for (int i = 0; i < 2; i++)
        #pragma unroll
        for (int j = 0; j < 4; j++)
            #pragma unroll
            for (int c = 0; c < 4; c++) acc[i][j][c] = 0.f;

    #pragma unroll
    for (int s = 0; s < NSTG - 1; s++) {
        const uint32_t dst = sb + s * ST;
        CP16(dst + o0, src0);
        CP16(dst + o1, src1);
        CP16(dst + CH + o0, src0 + 4096);
        CP16(dst + CH + o1, src1 + 2048);
        src0 += 8192; src1 += 4096;
        CP_COMMIT();
    }

    for (int s = 0; s < SP; s++) {
        CP_WAIT2();
        __syncthreads();

        const uint32_t stg = sb + (uint32_t)((s & 3) * ST);
        #pragma unroll
        for (int j = 0; j < 2; j++) {
            const uint32_t cofs = stg + j * CH;
            uint32_t aH[2][4], aL[2][4], bS[2][4];
            #pragma unroll
            for (int mf = 0; mf < 2; mf++) {
                LDSM4(aH[mf], cofs + aOffH[mf]);
                LDSM4(aL[mf], cofs + aOffH[mf] + 2048);
            }
            #pragma unroll
            for (int p = 0; p < 2; p++) LDSM4(bS[p], cofs + bOff[p]);

            #pragma unroll
            for (int mf = 0; mf < 2; mf++)
                #pragma unroll
                for (int nf = 0; nf < 4; nf++) {
                    const int p = nf >> 1, q = (nf & 1) * 2;
                    MMA_FP16(acc[mf][nf], aH[mf][0], aH[mf][1], aH[mf][2], aH[mf][3],
                             bS[p][q], bS[p][q + 1]);
                    MMA_FP16(acc[mf][nf], aL[mf][0], aL[mf][1], aL[mf][2], aL[mf][3],
                             bS[p][q], bS[p][q + 1]);
                }
        }

        if (s + NSTG - 1 < SP) {
            const uint32_t dst = sb + (uint32_t)(((s + NSTG - 1) & 3) * ST);
            CP16(dst + o0, src0);
            CP16(dst + o1, src1);
            CP16(dst + CH + o0, src0 + 4096);
            CP16(dst + CH + o1, src1 + 2048);
            src0 += 8192; src1 += 4096;
        }
        CP_COMMIT();
    }

    // ---- epilogue ----
    #pragma unroll
    for (int mf = 0; mf < 2; mf++) {
        const int r0 = bm + wm + mf * 16 + g;
        #pragma unroll
        for (int nf = 0; nf < 4; nf++) {
            const int c0 = bn + wn + nf * 8 + 2 * t4;
            const float2 bv = *(const float2*)(bias + c0);
            float v00 = acc[mf][nf][0] + bv.x;
            float v01 = acc[mf][nf][1] + bv.y;
            float v10 = acc[mf][nf][2] + bv.x;
            float v11 = acc[mf][nf][3] + bv.y;
            if (EPI == 2) {
                v00 = v00 * 0.5f * (1.0f + erff(v00 * 0.70710678118654752f));
                v01 = v01 * 0.5f * (1.0f + erff(v01 * 0.70710678118654752f));
                v10 = v10 * 0.5f * (1.0f + erff(v10 * 0.70710678118654752f));
                v11 = v11 * 0.5f * (1.0f + erff(v11 * 0.70710678118654752f));
                uint8_t* C = (uint8_t*)Cout;
                store_split2_f16(C, N, r0,     c0, v00, v01);
                store_split2_f16(C, N, r0 + 8, c0, v10, v11);
            } else if (EPI == 3) {
                const size_t i0 = (size_t)r0 * N + c0;
                const size_t i1 = (size_t)(r0 + 8) * N + c0;
                const float2 r0v = *(const float2*)(res + i0);
                const float2 r1v = *(const float2*)(res + i1);
                v00 += r0v.x; v01 += r0v.y; v10 += r1v.x; v11 += r1v.y;
                uint8_t* C = (uint8_t*)Cout;
                store_h2(C, N, r0,     c0, v00, v01);
                store_h2(C, N, r0 + 8, c0, v10, v11);
            } else {
                float* C = (float*)Cout;
                const size_t i0 = (size_t)r0 * N + c0;
                const size_t i1 = (size_t)(r0 + 8) * N + c0;
                if (EPI == 1) {
                    const float2 r0v = *(const float2*)(res + i0);
                    const float2 r1v = *(const float2*)(res + i1);
                    v00 += r0v.x; v01 += r0v.y; v10 += r1v.x; v11 += r1v.y;
                }
                *(float2*)(C + i0) = make_float2(v00, v01);
                *(float2*)(C + i1) = make_float2(v10, v11);
            }
        }
    }
}

// ---------------- fp16 single-term GEMM (vocab), 4 k-chunks/stage -----------
// TM=128 x 128. Stage = 4 chunks = 32 KB, 3 stages = 96 KB, 2 CTAs/SM.
__global__ __launch_bounds__(256, 2)
void gemm_h(const uint8_t* __restrict__ A, const uint8_t* __restrict__ W,
            const float* __restrict__ bias, float* __restrict__ C,
            int M, int N, int K) {
    constexpr int ST   = 32768;
    constexpr int NSTG = 3;

    extern __shared__ uint8_t smem[];
    const uint32_t sb = smem_u32(smem);

    const int tid = threadIdx.x;
    const int bm = blockIdx.x * 128;
    const int bn = blockIdx.y * 128;
    const int wid = tid >> 5, lane = tid & 31;
    const int g = lane >> 2, t4 = lane & 3;
    const int wm = (wid >> 2) * 64;
    const int wn = (wid & 3) * 32;

    const int S = K >> 4;        // 32 k-chunks
    const int SP = S >> 2;       // 8 pipeline stages

    const int o0 = tid * 16;
    const int o1 = 4096 + tid * 16;
    const uint8_t* src0;
    const uint8_t* src1;
    {
        const int mt0 = blockIdx.x * 2;
        const int nt0 = blockIdx.y * 2;
        const uint8_t* blkp[4];
        blkp[0] = A + (size_t)(mt0 + 0) * S * 2048;
        blkp[1] = A + (size_t)(mt0 + 1) * S * 2048;
        blkp[2] = W + (size_t)(nt0 + 0) * S * 2048;
        blkp[3] = W + (size_t)(nt0 + 1) * S * 2048;
        src0 = blkp[o0 >> 11] + (o0 & 2047);
        src1 = blkp[o1 >> 11] + (o1 & 2047);
    }

    const int sel = lane >> 3, ri = lane & 7;
    uint32_t aOff[4], bOff[2];
    #pragma unroll
    for (int mf = 0; mf < 4; mf++) {
        const int m = wm + mf * 16 + (sel & 1) * 8 + ri;
        aOff[mf] = tile_off_h(m, sel >> 1);
    }
    #pragma unroll
    for (int p = 0; p < 2; p++) {
        const int n = wn + p * 16 + (sel >> 1) * 8 + ri;
        bOff[p] = 4096 + tile_off_h(n, sel & 1);
    }

    float acc[4][4][4];
    #pragma unroll
    for (int i = 0; i < 4; i++)
        #pragma unroll
        for (int j = 0; j < 4; j++)
            #pragma unroll
            for (int c = 0; c < 4; c++) acc[i][j][c] = 0.f;

    #pragma unroll
    for (int s = 0; s < NSTG - 1; s++) {
        const uint32_t dst = sb + s * ST;
        #pragma unroll
        for (int c = 0; c < 4; c++) {
            CP16(dst + c * 8192 + o0, src0 + c * 2048);
            CP16(dst + c * 8192 + o1, src1 + c * 2048);
        }
        src0 += 8192; src1 += 8192;
        CP_COMMIT();
    }

    int cur = 0, nxt = 2;   // stage slots mod 3
    for (int s = 0; s < SP; s++) {
        CP_WAIT1();
        __syncthreads();

        const uint32_t stg = sb + (uint32_t)(cur * ST);
        #pragma unroll
        for (int j = 0; j < 4; j++) {
            const uint32_t cofs = stg + j * 8192;
            uint32_t aF[4][4], bF[2][4];
            #pragma unroll
            for (int mf = 0; mf < 4; mf++) LDSM4(aF[mf], cofs + aOff[mf]);
            #pragma unroll
            for (int p = 0; p < 2; p++)    LDSM4(bF[p], cofs + bOff[p]);

            #pragma unroll
            for (int mf = 0; mf < 4; mf++)
                #pragma unroll
                for (int nf = 0; nf < 4; nf++) {
                    const int p = nf >> 1, q = (nf & 1) * 2;
                    MMA_FP16(acc[mf][nf], aF[mf][0], aF[mf][1], aF[mf][2], aF[mf][3],
                             bF[p][q], bF[p][q + 1]);
                }
        }

        if (s + NSTG - 1 < SP) {
            const uint32_t dst = sb + (uint32_t)(nxt * ST);
            #pragma unroll
            for (int c = 0; c < 4; c++) {
                CP16(dst + c * 8192 + o0, src0 + c * 2048);
                CP16(dst + c * 8192 + o1, src1 + c * 2048);
            }
            src0 += 8192; src1 += 8192;
        }
        CP_COMMIT();
        cur = (cur == 2) ? 0 : cur + 1;
        nxt = (nxt == 2) ? 0 : nxt + 1;
    }

    #pragma unroll
    for (int mf = 0; mf < 4; mf++) {
        const int r0 = bm + wm + mf * 16 + g;
        #pragma unroll
        for (int nf = 0; nf < 4; nf++) {
            const int c0 = bn + wn + nf * 8 + 2 * t4;
            const float2 bv = *(const float2*)(bias + c0);
            const size_t i0 = (size_t)r0 * N + c0;
            const size_t i1 = (size_t)(r0 + 8) * N + c0;
            *(float2*)(C + i0) = make_float2(acc[mf][nf][0] + bv.x, acc[mf][nf][1] + bv.y);
            *(float2*)(C + i1) = make_float2(acc[mf][nf][2] + bv.x, acc[mf][nf][3] + bv.y);
        }
    }
}

// ---------------- launch ----------------
extern "C" void kernel_launch(void* const* d_in, const int* in_sizes, int n_in,
                              void* d_out, int out_size) {
    const float* patches        = (const float*)d_in[0];
    const float* masked_token   = (const float*)d_in[3];
    const float* partial_params = (const float*)d_in[4];
    const float* emb_w          = (const float*)d_in[5];
    const float* emb_b          = (const float*)d_in[6];
    const float* ln1_g          = (const float*)d_in[7];
    const float* ln1_b          = (const float*)d_in[8];
    const float* in_proj_w      = (const float*)d_in[9];
    const float* in_proj_b      = (const float*)d_in[10];
    const float* out_proj_w     = (const float*)d_in[11];
    const float* out_proj_b     = (const float*)d_in[12];
    const float* rel_pos        = (const float*)d_in[13];
    const float* ln2_g          = (const float*)d_in[14];
    const float* ln2_b          = (const float*)d_in[15];
    const float* ffn_w1         = (const float*)d_in[16];
    const float* ffn_b1         = (const float*)d_in[17];
    const float* ffn_w2         = (const float*)d_in[18];
    const float* ffn_b2         = (const float*)d_in[19];
    const float* outp_w         = (const float*)d_in[20];
    const float* outp_b         = (const float*)d_in[21];
    float* out = (float*)d_out;

    float *x, *qkv;
    uint8_t *xn, *o, *h, *xf, *win, *wo, *w1, *w2, *wv;
    cudaGetSymbolAddress((void**)&x,   g_x);
    cudaGetSymbolAddress((void**)&qkv, g_qkv);
    cudaGetSymbolAddress((void**)&xn,  s_xn);
    cudaGetSymbolAddress((void**)&o,   s_o);
    cudaGetSymbolAddress((void**)&h,   s_h);
    cudaGetSymbolAddress((void**)&xf,  s_xf);
    cudaGetSymbolAddress((void**)&win, s_win);
    cudaGetSymbolAddress((void**)&wo,  s_wo);
    cudaGetSymbolAddress((void**)&w1,  s_w1);
    cudaGetSymbolAddress((void**)&w2,  s_w2);
    cudaGetSymbolAddress((void**)&wv,  s_wv);

    cudaFuncSetAttribute(attn_kernel, cudaFuncAttributeMaxDynamicSharedMemorySize, ATTN_SMEM);
    cudaFuncSetAttribute((const void*)gemm_2t<0>, cudaFuncAttributeMaxDynamicSharedMemorySize, 65536);
    cudaFuncSetAttribute((const void*)gemm_2t<1>, cudaFuncAttributeMaxDynamicSharedMemorySize, 65536);
    cudaFuncSetAttribute((const void*)gemm_2t<2>, cudaFuncAttributeMaxDynamicSharedMemorySize, 65536);
    cudaFuncSetAttribute((const void*)gemm_2t<3>, cudaFuncAttributeMaxDynamicSharedMemorySize, 65536);
    cudaFuncSetAttribute((const void*)gemm_h, cudaFuncAttributeMaxDynamicSharedMemorySize, 98304);

    // ---- convert all weights to fp16 single tiles (per-chunk, round-14) ----
    {
        int nc;
        nc = NL * 3 * ND * ND / 8;  convert_w_h<<<(nc + 255) / 256, 256>>>(in_proj_w,  win, ND, nc);
        nc = NL * ND * ND / 8;      convert_w_h<<<(nc + 255) / 256, 256>>>(out_proj_w, wo,  ND, nc);
        nc = NL * NF * ND / 8;      convert_w_h<<<(nc + 255) / 256, 256>>>(ffn_w1,     w1,  ND, nc);
        nc = NL * ND * NF / 8;      convert_w_h<<<(nc + 255) / 256, 256>>>(ffn_w2,     w2,  NF, nc);
        nc = (int)((size_t)NV * ND / 8);
        convert_w_h<<<(nc + 255) / 256, 256>>>(outp_w, wv, ND, nc);
    }

    tokenize_embed_kernel<<<NTOK, 128>>>(patches, masked_token, partial_params, emb_w, emb_b);

    for (int l = 0; l < NL; l++) {
        ln_kernel<<<NTOK, 256>>>(x, xn, ln1_g + l * ND, ln1_b + l * ND);

        gemm_2t<0><<<dim3(NTOK / 64, 3 * ND / 128), 256, 65536>>>(
            xn, win + (size_t)l * 3 * ND * ND * 2, in_proj_b + l * 3 * ND,
            nullptr, qkv, NTOK, 3 * ND, ND);

        attn_kernel<<<NB * NH * 2, 512, ATTN_SMEM>>>(rel_pos + (size_t)l * NS * NS);

        gemm_2t<1><<<dim3(NTOK / 64, ND / 128), 256, 65536>>>(
            o, wo + (size_t)l * ND * ND * 2, out_proj_b + l * ND,
            x, x, NTOK, ND, ND);

        ln_kernel<<<NTOK, 256>>>(x, xn, ln2_g + l * ND, ln2_b + l * ND);

        gemm_2t<2><<<dim3(NTOK / 64, NF / 128), 256, 65536>>>(
            xn, w1 + (size_t)l * NF * ND * 2, ffn_b1 + l * NF,
            nullptr, h, NTOK, NF, ND);

        if (l < NL - 1) {
            gemm_2t<1><<<dim3(NTOK / 64, ND / 128), 256, 65536>>>(
                h, w2 + (size_t)l * ND * NF * 2, ffn_b2 + l * ND,
                x, x, NTOK, ND, NF);
        } else {
            gemm_2t<3><<<dim3(NTOK / 64, ND / 128), 256, 65536>>>(
                h, w2 + (size_t)l * ND * NF * 2, ffn_b2 + l * ND,
                x, xf, NTOK, ND, NF);
        }
    }

    gemm_h<<<dim3(NTOK / 128, NV / 128), 256, 98304>>>(
        xf, wv, outp_b, out, NTOK, NV, ND);
}